// round 1
// baseline (speedup 1.0000x reference)
#include <cuda_runtime.h>
#include <math_constants.h>

// Problem constants (fixed by setup_inputs): B=16, Hr*Wr=R=4096, Hq*Wq=Q=1024
#define R 4096
#define Q 1024
#define MAXB 16
#define RCHUNK 128
#define NCHUNK 32   // R / RCHUNK

// Scratch: per-chunk partial column sums and final log column sums.
// Layout g_part[c][b*Q + q] so pass-1 writes are coalesced.
__device__ float g_part[NCHUNK * MAXB * Q];     // 2 MB
__device__ float g_creflog[MAXB * Q];           // 64 KB

// ---------------------------------------------------------------------------
// Pass 1: partial column sums of exp(ar * x) over 128-row chunks.
// Block = 256 threads, each thread owns 4 consecutive q (one float4 column
// group) and streams 128 rows. Loads are perfectly coalesced (one 4KB row
// per block iteration).
// ---------------------------------------------------------------------------
__global__ __launch_bounds__(256) void qatm_pass1(
    const float* __restrict__ x, const float* __restrict__ coef_ref)
{
    const int blk = blockIdx.x;
    const int b = blk >> 5;          // / NCHUNK
    const int c = blk & (NCHUNK - 1);
    const int t = threadIdx.x;       // 0..255

    const float ar = coef_ref[0];

    const float4* p = reinterpret_cast<const float4*>(
        x + ((size_t)b * R + (size_t)c * RCHUNK) * Q) + t;

    float4 acc = make_float4(0.f, 0.f, 0.f, 0.f);

    // 128 rows, 4-way unrolled for MLP (4 independent float4 loads in flight)
    #pragma unroll 1
    for (int r = 0; r < RCHUNK; r += 4) {
        float4 v0 = p[0 * (Q / 4)];
        float4 v1 = p[1 * (Q / 4)];
        float4 v2 = p[2 * (Q / 4)];
        float4 v3 = p[3 * (Q / 4)];
        p += 4 * (Q / 4);
        acc.x += __expf(ar * v0.x); acc.y += __expf(ar * v0.y);
        acc.z += __expf(ar * v0.z); acc.w += __expf(ar * v0.w);
        acc.x += __expf(ar * v1.x); acc.y += __expf(ar * v1.y);
        acc.z += __expf(ar * v1.z); acc.w += __expf(ar * v1.w);
        acc.x += __expf(ar * v2.x); acc.y += __expf(ar * v2.y);
        acc.z += __expf(ar * v2.z); acc.w += __expf(ar * v2.w);
        acc.x += __expf(ar * v3.x); acc.y += __expf(ar * v3.y);
        acc.z += __expf(ar * v3.z); acc.w += __expf(ar * v3.w);
    }

    float4* outp = reinterpret_cast<float4*>(g_part + (size_t)c * (MAXB * Q));
    outp[b * (Q / 4) + t] = acc;
}

// ---------------------------------------------------------------------------
// Reduce 32 chunk partials per column and take log -> Cref.
// ---------------------------------------------------------------------------
__global__ __launch_bounds__(256) void qatm_colreduce(int ncols)
{
    int col = blockIdx.x * 256 + threadIdx.x;
    if (col >= ncols) return;
    float s = 0.f;
    #pragma unroll
    for (int c = 0; c < NCHUNK; ++c)
        s += g_part[c * (MAXB * Q) + col];
    g_creflog[col] = __logf(s);
}

// ---------------------------------------------------------------------------
// Pass 2: one warp per row. In a single read of the 4KB row, compute
//   s = sum_q exp(aq * x)            (row softmax denominator)
//   m = max_q ((ar+aq)*x - Cref[q])  (log of the max joint numerator)
// then out[row] = exp(0.5 * (m - log s)).
// Cref for this b is staged in 4KB of shared memory per block.
// ---------------------------------------------------------------------------
__global__ __launch_bounds__(256) void qatm_pass2(
    const float* __restrict__ x,
    const float* __restrict__ coef_ref,
    const float* __restrict__ coef_qry,
    float* __restrict__ out)
{
    __shared__ __align__(16) float s_clog[Q];

    const int wid  = threadIdx.x >> 5;
    const int lane = threadIdx.x & 31;
    const int row0 = blockIdx.x * 8;       // 8 rows per block (8 warps)
    const int b    = row0 >> 12;           // / R ; same b for all 8 rows

    // Stage Cref[b][*] into shared memory
    const float4* cl = reinterpret_cast<const float4*>(g_creflog + (size_t)b * Q);
    float4* sc = reinterpret_cast<float4*>(s_clog);
    if (threadIdx.x < Q / 4) sc[threadIdx.x] = cl[threadIdx.x];
    __syncthreads();

    const float ar = coef_ref[0];
    const float aq = coef_qry[0];
    const float cc = ar + aq;

    const int row = row0 + wid;
    const float4* p = reinterpret_cast<const float4*>(x + (size_t)row * Q);

    float s = 0.f;
    float m = -CUDART_INF_F;

    #pragma unroll
    for (int it = 0; it < 8; ++it) {
        int q4 = it * 32 + lane;
        float4 v = p[q4];
        float4 cg = sc[q4];
        s += __expf(aq * v.x);
        s += __expf(aq * v.y);
        s += __expf(aq * v.z);
        s += __expf(aq * v.w);
        float m0 = fmaxf(fmaf(cc, v.x, -cg.x), fmaf(cc, v.y, -cg.y));
        float m1 = fmaxf(fmaf(cc, v.z, -cg.z), fmaf(cc, v.w, -cg.w));
        m = fmaxf(m, fmaxf(m0, m1));
    }

    #pragma unroll
    for (int o = 16; o > 0; o >>= 1) {
        s += __shfl_xor_sync(0xFFFFFFFFu, s, o);
        m = fmaxf(m, __shfl_xor_sync(0xFFFFFFFFu, m, o));
    }

    if (lane == 0)
        out[row] = __expf(0.5f * (m - __logf(s)));
}

// ---------------------------------------------------------------------------
extern "C" void kernel_launch(void* const* d_in, const int* in_sizes, int n_in,
                              void* d_out, int out_size)
{
    const float* x  = (const float*)d_in[0];
    const float* cr = (const float*)d_in[1];
    const float* cq = (const float*)d_in[2];
    float* out = (float*)d_out;

    int B = in_sizes[0] / (R * Q);   // 16

    qatm_pass1<<<B * NCHUNK, 256>>>(x, cr);
    qatm_colreduce<<<(B * Q + 255) / 256, 256>>>(B * Q);
    qatm_pass2<<<(B * R) / 8, 256>>>(x, cr, cq, out);
}